// round 5
// baseline (speedup 1.0000x reference)
#include <cuda_runtime.h>
#include <cuda_bf16.h>

// Problem constants
#define B_   8192
#define M_   50000
#define NU_  16
#define F_   128
#define E_   65536
#define C1_  4096                          // rows copied in K3 (alongside scatter)

#define SCATTER_BLOCKS ((E_ * 32) / 512)   // 4096
#define K3_GRID (SCATTER_BLOCKS + C1_)     // 8192

#define K4_GRID 11476                      // 4 copy rows per block: 4*11476 = 45904 = M_-C1_
#define K4_ROWS 4

// Scratch (device globals — no allocation allowed)
__device__ float4 g_h1agg4[B_ * (F_ / 4)];   // h1_agg  [B,F]
__device__ float4 g_h2agg4[B_ * (F_ / 4)];   // h2_agg  [B,F]
__device__ int    g_winner[M_];              // winning b per V_n row (max b), -1 if untouched

// ---------------------------------------------------------------------------
// K1: init scratch (every replay — deterministic)
// ---------------------------------------------------------------------------
__global__ void init_kernel() {
    int t = blockIdx.x * blockDim.x + threadIdx.x;
    const int NV = B_ * (F_ / 4);  // 262144
    if (t < NV) {
        g_h1agg4[t] = make_float4(0.f, 0.f, 0.f, 0.f);
        g_h2agg4[t] = make_float4(0.f, 0.f, 0.f, 0.f);
    }
    if (t < M_) g_winner[t] = -1;
}

// ---------------------------------------------------------------------------
// K2: winner resolution (last-update-wins == max b wins)
// ---------------------------------------------------------------------------
__global__ void winner_kernel(const int* __restrict__ v_idx) {
    int b = blockIdx.x * blockDim.x + threadIdx.x;
    if (b < B_) atomicMax(&g_winner[v_idx[b]], b);
}

// ---------------------------------------------------------------------------
// K3: fused, parity-striped — even bids scatter, odd bids copy rows [0, C1_)
// ---------------------------------------------------------------------------
__global__ __launch_bounds__(512)
void k3_scatter_copy(const float4* __restrict__ h1_4,
                     const int*    __restrict__ h1_idx,
                     const float4* __restrict__ h2_4,
                     const int*    __restrict__ h2_idx,
                     const float*  __restrict__ Vn,
                     float*        __restrict__ vout) {
    int bid = blockIdx.x;
    if ((bid & 1) == 0) {
        int t = (bid >> 1) * 512 + threadIdx.x;  // t in [0, E*32)
        int e = t >> 5;
        int c = t & 31;
        float4 a = __ldcs(h1_4 + t);
        float4 b = __ldcs(h2_4 + t);
        int ia = __ldg(h1_idx + e) * 32 + c;
        int ib = __ldg(h2_idx + e) * 32 + c;
        atomicAdd(&g_h1agg4[ia], a);
        atomicAdd(&g_h2agg4[ib], b);
    } else {
        int row = bid >> 1;                      // rows [0, C1_)
        if (g_winner[row] < 0) {
            const float4* src = (const float4*)(Vn   + (size_t)row * (NU_ * F_));
            float4*       dst = (float4*)      (vout + (size_t)row * (NU_ * F_));
            __stcs(dst + threadIdx.x, __ldcs(src + threadIdx.x));
        }
    }
}

// ---------------------------------------------------------------------------
// K4: homogeneous blocks — every block copies K4_ROWS rows; blocks [0,B_)
//     additionally compute energy(b=bid). Copy loads are batched (MLP=4) so
//     each block's streaming traffic hides its own energy-gather latency.
// ---------------------------------------------------------------------------
__global__ __launch_bounds__(512)
void k4_energy_copy(const float*  __restrict__ mo,
                    const float*  __restrict__ Vn,
                    const int*    __restrict__ v_idx,
                    const float*  __restrict__ gram,
                    float*        __restrict__ energy_out,
                    float*        __restrict__ vout) {
    int bid  = blockIdx.x;
    int lane = threadIdx.x & 31;
    int u    = threadIdx.x >> 5;   // 0..15
    bool has_energy = (bid < B_);

    __shared__ float ov_s[16], le_s[16], dn_s[16];

    // ---- energy loads issued first (long-latency gather) ----
    int row = 0;
    float4 v, m, a1, a2;
    if (has_energy) {
        row = __ldg(v_idx + bid);
        const float4* vrow = (const float4*)(Vn + ((size_t)row * NU_ + u) * F_);
        v  = vrow[lane];
        int i = bid * 32 + lane;
        m  = __ldg((const float4*)mo + i);
        a1 = g_h1agg4[i];
        a2 = g_h2agg4[i];
    }

    // ---- batched copy loads (independent, fill the memory pipe) ----
    float4 c[K4_ROWS];
    bool   w[K4_ROWS];
    #pragma unroll
    for (int j = 0; j < K4_ROWS; j++) {
        int r = C1_ + bid + j * K4_GRID;         // always < M_
        w[j] = (g_winner[r] < 0);
        if (w[j])
            c[j] = __ldcs((const float4*)(Vn + (size_t)r * (NU_ * F_)) + threadIdx.x);
    }
    // ---- copy stores ----
    #pragma unroll
    for (int j = 0; j < K4_ROWS; j++) {
        int r = C1_ + bid + j * K4_GRID;
        if (w[j])
            __stcs((float4*)(vout + (size_t)r * (NU_ * F_)) + threadIdx.x, c[j]);
    }

    if (!has_energy) return;

    // ---- energy compute (operands long in flight by now) ----
    float4 f = make_float4(m.x + a1.x, m.y + a1.y, m.z + a1.z, m.w + a1.w); // feats
    float4 g = make_float4(f.x + a2.x, f.y + a2.y, f.z + a2.z, f.w + a2.w); // feats+h2

    float ov = v.x * m.x + v.y * m.y + v.z * m.z + v.w * m.w;   // overlap partial
    float le = v.x * g.x + v.y * g.y + v.z * g.z + v.w * g.w;   // loc_energy partial
    #pragma unroll
    for (int o = 16; o; o >>= 1) {
        ov += __shfl_xor_sync(0xFFFFFFFF, ov, o);
        le += __shfl_xor_sync(0xFFFFFFFF, le, o);
    }
    if (lane == 0) { ov_s[u] = ov; le_s[u] = le; }
    __syncthreads();

    // warp 0: denom = gram[b] @ overlap (16x16 matvec), p-weights, energy
    if (u == 0) {
        float d = 0.f, l = 0.f;
        if (lane < 16) {
            const float* gr = gram + (size_t)bid * (NU_ * NU_) + lane * NU_;
            #pragma unroll
            for (int vv = 0; vv < 16; vv++) d += gr[vv] * ov_s[vv];
            l = le_s[lane];
        }
        float d2 = d * d;
        float ns = l * d2;   // lanes >=16 contribute 0
        float ds = d2;
        #pragma unroll
        for (int o = 16; o; o >>= 1) {
            ns += __shfl_xor_sync(0xFFFFFFFF, ns, o);
            ds += __shfl_xor_sync(0xFFFFFFFF, ds, o);
        }
        if (lane < 16) dn_s[lane] = d;
        if (lane == 0) energy_out[bid] = ns / ds;
    }
    __syncthreads();

    // winner block writes top_states = tanh(V + denom[u]*feats)
    if (g_winner[row] == bid) {
        float  dn = dn_s[u];
        float4 t;
        t.x = tanhf(v.x + dn * f.x);
        t.y = tanhf(v.y + dn * f.y);
        t.z = tanhf(v.z + dn * f.z);
        t.w = tanhf(v.w + dn * f.w);
        __stcs((float4*)(vout + ((size_t)row * NU_ + u) * F_) + lane, t);
    }
}

// ---------------------------------------------------------------------------
extern "C" void kernel_launch(void* const* d_in, const int* in_sizes, int n_in,
                              void* d_out, int out_size) {
    const float* mo    = (const float*)d_in[0];
    const float* Vn    = (const float*)d_in[1];
    const int*   vidx  = (const int*)  d_in[2];
    const float* h1    = (const float*)d_in[3];
    const int*   h1i   = (const int*)  d_in[4];
    const float* h2    = (const float*)d_in[5];
    const int*   h2i   = (const int*)  d_in[6];
    const float* gram  = (const float*)d_in[7];

    float* energy = (float*)d_out;        // [B]
    float* vout   = energy + B_;          // [M, NU, F]

    {   // K1: zero aggregates, winner=-1
        int n = B_ * (F_ / 4);            // 262144 (>= M_)
        init_kernel<<<(n + 511) / 512, 512>>>();
    }
    // K2: resolve winners
    winner_kernel<<<(B_ + 255) / 256, 256>>>(vidx);

    // K3: scatter ∥ copy[0, C1), parity-striped
    k3_scatter_copy<<<K3_GRID, 512>>>(
        (const float4*)h1, h1i, (const float4*)h2, h2i, Vn, vout);

    // K4: homogeneous energy+copy blocks over rows [C1, M)
    k4_energy_copy<<<K4_GRID, 512>>>(mo, Vn, vidx, gram, energy, vout);
}